// round 16
// baseline (speedup 1.0000x reference)
#include <cuda_runtime.h>
#include <math.h>

#define TPB   768
#define BM    4
#define S_LEN 128
#define B_TOT 512
#define H     192
#define VOC   256
#define PP    64
#define PHH   16

#define KB1   256   // folded bind1 K: [prev|pw]           (tok folded into E_bind)
#define KS1   288   // folded succ1 K: [sec|pw|phw|pad16]

// output buffer offsets (floats), concatenated in reference-return order
#define OFF_LOGITS 0
#define OFF_HIDDEN (512*128*256)
#define OFF_PW     (OFF_HIDDEN + 512*128*192)
#define OFF_PHW    (OFF_PW     + 512*128*64)
#define OFF_GATE   (OFF_PHW    + 512*128*16)

__device__ float g_CB1 [KB1 * H];   // folded bind1 weights ([prev|pw] blocks)
__device__ float g_CS1 [KS1 * H];   // folded succ1 weights
__device__ float g_Esel[VOC * PP];  // emb @ sel_W_tok + sel_b
__device__ float g_Ebind[VOC * H];  // emb @ bind_W1_tok + bind_b1

__device__ __forceinline__ float geluf(float x) {
    return 0.5f * x * (1.0f + erff(x * 0.7071067811865475f));
}

// ---------------------------------------------------------------------------
// prep: build folded weights + per-vocab token projections (once per launch)
// ---------------------------------------------------------------------------
#define PREP_TOTAL (KB1*H + KS1*H + VOC*PP + VOC*H)

__global__ void prep_kernel(const float* __restrict__ emb,
                            const float* __restrict__ pv,
                            const float* __restrict__ pe,
                            const float* __restrict__ selW,
                            const float* __restrict__ selb,
                            const float* __restrict__ bw1,
                            const float* __restrict__ bb1,
                            const float* __restrict__ sw1)
{
    int idx = blockIdx.x * blockDim.x + threadIdx.x;
    if (idx >= PREP_TOTAL) return;

    if (idx < KB1 * H) {                         // CB1: [prev(192) | pw(64)] x H
        const int row = idx / H, n = idx % H;
        float v;
        if (row < H) v = bw1[(2 * H + row) * H + n];          // prev block
        else {
            const int p = row - H;
            float a = 0.f, b = 0.f;
            for (int h = 0; h < H; h += 2) {
                a = fmaf(pv[p * H + h],     bw1[(H + h) * H + n],     a);
                b = fmaf(pv[p * H + h + 1], bw1[(H + h + 1) * H + n], b);
            }
            v = a + b;
        }
        g_CB1[row * H + n] = v;
        return;
    }
    idx -= KB1 * H;
    if (idx < KS1 * H) {                         // CS1: [sec|pw|phw|pad16]
        const int r = idx / H, n = idx % H;
        float v;
        if (r < H) v = sw1[r * H + n];
        else if (r < H + PP) {
            const int p = r - H;
            float a = 0.f, b = 0.f;
            for (int h = 0; h < H; h += 2) {
                a = fmaf(pv[p * H + h],     sw1[(H + h) * H + n],     a);
                b = fmaf(pv[p * H + h + 1], sw1[(H + h + 1) * H + n], b);
            }
            v = a + b;
        } else if (r < H + PP + PHH) {
            const int q = r - H - PP;
            float a = 0.f, b = 0.f;
            for (int h = 0; h < H; h += 2) {
                a = fmaf(pe[q * H + h],     sw1[(2 * H + h) * H + n],     a);
                b = fmaf(pe[q * H + h + 1], sw1[(2 * H + h + 1) * H + n], b);
            }
            v = a + b;
        } else v = 0.f;
        g_CS1[r * H + n] = v;
        return;
    }
    idx -= KS1 * H;
    if (idx < VOC * PP) {                        // Esel = emb @ sel_W_tok + sel_b
        const int vid = idx / PP, n = idx % PP;
        float a = 0.f, b = 0.f;
        for (int h = 0; h < H; h += 2) {
            a = fmaf(emb[vid * H + h],     selW[h * PP + n],       a);
            b = fmaf(emb[vid * H + h + 1], selW[(h + 1) * PP + n], b);
        }
        g_Esel[vid * PP + n] = a + b + selb[n];
        return;
    }
    idx -= VOC * PP;
    {                                            // Ebind = emb @ bind_W1_tok + bind_b1
        const int vid = idx / H, n = idx % H;
        float a = 0.f, b = 0.f;
        for (int h = 0; h < H; h += 2) {
            a = fmaf(emb[vid * H + h],     bw1[h * H + n],       a);
            b = fmaf(emb[vid * H + h + 1], bw1[(h + 1) * H + n], b);
        }
        g_Ebind[vid * H + n] = a + b + bb1[n];
    }
}

struct __align__(16) Smem {
    float red [12288];          // k-split partial scratch: NSEG*BM*N == 12288 for all shapes
    float xb_bind [BM * KB1];   // [prev | pw]
    float xb_router[BM * 384];  // [sec | prev]
    float xb_succ [BM * KS1];   // [sec | pw | phw | pad16]
    float xb_gate [BM * 384];   // [succ | prev]
    float xb_dec  [BM * H];     // hidden (also sel input)
    float hbuf [BM * H];        // bind1/succ1/gate1 intermediate
    float prev [BM * H];        // normal copy for LN
    float succ [BM * H];        // normal copy for LN
    float z64  [BM * PP];
    float z16  [BM * PHH];
    float sgw2 [H];             // gate_W2 cached in smem
    float slng [H];             // ln_g cached
    float slnb [H];             // ln_b cached
    float sWsel[H * PP];        // selW_prev cached (48KB) — kills sel-phase ramp
    float sWrtr[384 * PHH];     // router_W cached (24KB) — kills router-phase ramp
    float sgb2;                 // gate_b2 scalar
    int   ids  [BM];            // ids(s)
};

// C[BM x N] = act( X[BM x K] @ W[K x N] (+ bias | + rowbias[ids[r]]) )
// thread -> (col4 = t % (N/4), kseg = t / (N/4)); partials reduced through smem.
// ACT: 0 = none, 1 = gelu(exact), 2 = tanh.  WSM: weights live in shared memory.
template<int K, int N, int ACT, bool HASB, bool ROWB, bool WSM>
__device__ __forceinline__ void gemm(const float* __restrict__ xs,
                                     const float* __restrict__ W,
                                     const float* __restrict__ bias,
                                     const float* __restrict__ rbias,
                                     const int*   __restrict__ ids,
                                     float* __restrict__ red,
                                     float* __restrict__ o1, int rs1, int off1,
                                     float* __restrict__ o2, int rs2, int off2,
                                     float* __restrict__ outg, int g_rstride)
{
    constexpr int NC4  = N / 4;
    constexpr int NSEG = TPB / NC4;
    constexpr int KS   = K / NSEG;
    static_assert(NC4 * NSEG == TPB, "thread mapping must be exact");
    static_assert(KS * NSEG == K,    "k split must be exact");
    static_assert((NSEG % 2) == 0,   "epilogue 2-acc split must be exact");

    const int t   = threadIdx.x;
    const int c4  = t % NC4;
    const int seg = t / NC4;
    const float4* __restrict__ Wv = reinterpret_cast<const float4*>(W);

    auto ldw = [&](int idx) -> float4 {
        if (WSM) return Wv[idx];
        else     return __ldg(&Wv[idx]);
    };

    float4 acc[BM];
#pragma unroll
    for (int r = 0; r < BM; r++) acc[r] = make_float4(0.f, 0.f, 0.f, 0.f);

    const int k0 = seg * KS;

    if constexpr ((KS % 4) == 0) {
        const float4* __restrict__ Xv = reinterpret_cast<const float4*>(xs);
#pragma unroll 2
        for (int kk4 = 0; kk4 < KS / 4; kk4++) {
            const int k = k0 + kk4 * 4;
            float4 xv[BM];
#pragma unroll
            for (int r = 0; r < BM; r++) xv[r] = Xv[(r * K + k) >> 2];
            // all four weight loads issued up front -> deeper MLP on the LDG stream
            float4 w0 = ldw((k + 0) * NC4 + c4);
            float4 w1 = ldw((k + 1) * NC4 + c4);
            float4 w2 = ldw((k + 2) * NC4 + c4);
            float4 w3 = ldw((k + 3) * NC4 + c4);
#pragma unroll
            for (int r = 0; r < BM; r++) {
                acc[r].x = fmaf(xv[r].x, w0.x, acc[r].x);
                acc[r].y = fmaf(xv[r].x, w0.y, acc[r].y);
                acc[r].z = fmaf(xv[r].x, w0.z, acc[r].z);
                acc[r].w = fmaf(xv[r].x, w0.w, acc[r].w);
                acc[r].x = fmaf(xv[r].y, w1.x, acc[r].x);
                acc[r].y = fmaf(xv[r].y, w1.y, acc[r].y);
                acc[r].z = fmaf(xv[r].y, w1.z, acc[r].z);
                acc[r].w = fmaf(xv[r].y, w1.w, acc[r].w);
            }
#pragma unroll
            for (int r = 0; r < BM; r++) {
                acc[r].x = fmaf(xv[r].z, w2.x, acc[r].x);
                acc[r].y = fmaf(xv[r].z, w2.y, acc[r].y);
                acc[r].z = fmaf(xv[r].z, w2.z, acc[r].z);
                acc[r].w = fmaf(xv[r].z, w2.w, acc[r].w);
                acc[r].x = fmaf(xv[r].w, w3.x, acc[r].x);
                acc[r].y = fmaf(xv[r].w, w3.y, acc[r].y);
                acc[r].z = fmaf(xv[r].w, w3.z, acc[r].z);
                acc[r].w = fmaf(xv[r].w, w3.w, acc[r].w);
            }
        }
    } else if constexpr ((KS % 2) == 0) {
        const float2* __restrict__ Xv = reinterpret_cast<const float2*>(xs);
#pragma unroll 3
        for (int kk2 = 0; kk2 < KS / 2; kk2++) {
            const int k = k0 + kk2 * 2;
            float2 xv[BM];
#pragma unroll
            for (int r = 0; r < BM; r++) xv[r] = Xv[(r * K + k) >> 1];
            float4 w0 = ldw((k + 0) * NC4 + c4);
            float4 w1 = ldw((k + 1) * NC4 + c4);
#pragma unroll
            for (int r = 0; r < BM; r++) {
                acc[r].x = fmaf(xv[r].x, w0.x, acc[r].x);
                acc[r].y = fmaf(xv[r].x, w0.y, acc[r].y);
                acc[r].z = fmaf(xv[r].x, w0.z, acc[r].z);
                acc[r].w = fmaf(xv[r].x, w0.w, acc[r].w);
                acc[r].x = fmaf(xv[r].y, w1.x, acc[r].x);
                acc[r].y = fmaf(xv[r].y, w1.y, acc[r].y);
                acc[r].z = fmaf(xv[r].y, w1.z, acc[r].z);
                acc[r].w = fmaf(xv[r].y, w1.w, acc[r].w);
            }
        }
    } else {
#pragma unroll
        for (int kk = 0; kk < KS; kk++) {
            const int k = k0 + kk;
            float4 w = ldw(k * NC4 + c4);
#pragma unroll
            for (int r = 0; r < BM; r++) {
                float x = xs[r * K + k];
                acc[r].x = fmaf(x, w.x, acc[r].x);
                acc[r].y = fmaf(x, w.y, acc[r].y);
                acc[r].z = fmaf(x, w.z, acc[r].z);
                acc[r].w = fmaf(x, w.w, acc[r].w);
            }
        }
    }

    float4* redv = reinterpret_cast<float4*>(red);
#pragma unroll
    for (int r = 0; r < BM; r++) redv[(seg * BM + r) * NC4 + c4] = acc[r];
    __syncthreads();

    for (int i = t; i < BM * N; i += TPB) {
        const int r = i / N;
        const int n = i % N;
        float v;
        if constexpr ((NSEG % 4) == 0) {
            float v0 = 0.f, v1 = 0.f, v2 = 0.f, v3 = 0.f;
#pragma unroll
            for (int g = 0; g < NSEG; g += 4) {
                v0 += red[((g + 0) * BM + r) * N + n];
                v1 += red[((g + 1) * BM + r) * N + n];
                v2 += red[((g + 2) * BM + r) * N + n];
                v3 += red[((g + 3) * BM + r) * N + n];
            }
            v = (v0 + v1) + (v2 + v3);
        } else {
            float v0 = 0.f, v1 = 0.f;
#pragma unroll
            for (int g = 0; g < NSEG; g += 2) {
                v0 += red[((g + 0) * BM + r) * N + n];
                v1 += red[((g + 1) * BM + r) * N + n];
            }
            v = v0 + v1;
        }
        if (HASB) v += __ldg(&bias[n]);
        if (ROWB) v += __ldg(&rbias[ids[r] * N + n]);
        if (ACT == 1) v = geluf(v);
        if (ACT == 2) v = tanhf(v);
        if (o1) o1[r * rs1 + off1 + n] = v;
        if (o2) o2[r * rs2 + off2 + n] = v;
        if (outg) outg[r * g_rstride + n] = v;
    }
    __syncthreads();
}

// warp-per-row softmax over N (<= 64): fan-out to two smem slots + global
template<int N>
__device__ __forceinline__ void softmax_rows(const float* __restrict__ z,
                                             float* __restrict__ o1, int rs1, int off1,
                                             float* __restrict__ o2, int rs2, int off2,
                                             float* __restrict__ outg, int g_rstride)
{
    const int w = threadIdx.x >> 5, lane = threadIdx.x & 31;
    if (w < BM) {
        const float* row = z + w * N;
        constexpr int PER = (N + 31) / 32;
        float m = -3.0e38f;
#pragma unroll
        for (int i = 0; i < PER; i++) {
            int n = lane + 32 * i;
            if (n < N) m = fmaxf(m, row[n]);
        }
#pragma unroll
        for (int o = 16; o; o >>= 1) m = fmaxf(m, __shfl_xor_sync(0xffffffffu, m, o));
        float ev[PER];
        float sum = 0.f;
#pragma unroll
        for (int i = 0; i < PER; i++) {
            int n = lane + 32 * i;
            if (n < N) { ev[i] = expf(row[n] - m); sum += ev[i]; }
        }
#pragma unroll
        for (int o = 16; o; o >>= 1) sum += __shfl_xor_sync(0xffffffffu, sum, o);
        const float inv = 1.f / sum;
#pragma unroll
        for (int i = 0; i < PER; i++) {
            int n = lane + 32 * i;
            if (n < N) {
                float v = ev[i] * inv;
                o1[w * rs1 + off1 + n] = v;
                o2[w * rs2 + off2 + n] = v;
                outg[w * g_rstride + n] = v;
            }
        }
    }
}

__global__ void __launch_bounds__(TPB, 1)
spike_kernel(const int* __restrict__ ids_g,
             const float* __restrict__ selW_prev,            // sel_W rows [H:2H)
             const float* __restrict__ bind_W2,  const float* __restrict__ bind_b2,
             const float* __restrict__ router_W, const float* __restrict__ router_b,
             const float* __restrict__ succ_b1,
             const float* __restrict__ succ_W2,  const float* __restrict__ succ_b2,
             const float* __restrict__ gate_W1,  const float* __restrict__ gate_b1,
             const float* __restrict__ gate_W2,  const float* __restrict__ gate_b2,
             const float* __restrict__ ln_g,     const float* __restrict__ ln_b,
             const float* __restrict__ dec_W,
             float* __restrict__ out)
{
    __shared__ Smem sm;
    const int t  = threadIdx.x;
    const int b0 = blockIdx.x * BM;

    float* out_logits = out + OFF_LOGITS;
    float* out_hidden = out + OFF_HIDDEN;
    float* out_pw     = out + OFF_PW;
    float* out_phw    = out + OFF_PHW;
    float* out_gate   = out + OFF_GATE;

    // init: zero prev slots + hidden + succ1 pad ; cache small vectors + small weights
    {
        const int r = t / H, h = t % H;
        sm.prev[t] = 0.f;
        sm.xb_dec[t] = 0.f;
        sm.xb_bind  [r * KB1 + h] = 0.f;       // prev slot of bind input
        sm.xb_router[r * 384 + H + h] = 0.f;
        sm.xb_gate  [r * 384 + H + h] = 0.f;
        if (t < H) {
            sm.sgw2[t] = __ldg(&gate_W2[t]);
            sm.slng[t] = __ldg(&ln_g[t]);
            sm.slnb[t] = __ldg(&ln_b[t]);
        }
        if (t == 0) sm.sgb2 = __ldg(&gate_b2[0]);
        if (t < BM * 16) {                      // pad slots [272:288) of xb_succ
            const int rr = t / 16, i = t % 16;
            sm.xb_succ[rr * KS1 + 272 + i] = 0.f;
        }
        // cache sel/router weights in smem (float4 copies)
        const float4* gs = reinterpret_cast<const float4*>(selW_prev);
        float4*       ds = reinterpret_cast<float4*>(sm.sWsel);
        for (int i = t; i < (H * PP) / 4; i += TPB) ds[i] = __ldg(&gs[i]);
        const float4* gr = reinterpret_cast<const float4*>(router_W);
        float4*       dr = reinterpret_cast<float4*>(sm.sWrtr);
        for (int i = t; i < (384 * PHH) / 4; i += TPB) dr[i] = __ldg(&gr[i]);
    }
    __syncthreads();

    for (int s = 0; s < S_LEN; s++) {
        // stage ids(s); published by the sel gemm's internal barrier
        if (t < BM) sm.ids[t] = __ldg(&ids_g[(b0 + t) * S_LEN + s]);

        // patch selector (tok folded, smem weights): pw = softmax(prev @ selW_prev + E_sel[id])
        gemm<H, PP, 0, false, true, true>(sm.xb_dec, sm.sWsel, nullptr, g_Esel, sm.ids, sm.red,
                                          sm.z64, PP, 0, nullptr, 0, 0, nullptr, 0);
        softmax_rows<PP>(sm.z64,
                         sm.xb_bind, KB1, H,         // pw slot of bind1 input
                         sm.xb_succ, KS1, H,         // pw slot of succ1 input
                         out_pw + (b0 * S_LEN + s) * PP, S_LEN * PP);
        __syncthreads();

        // section binder (tok+patch folded): tanh(gelu([prev,pw]@CB1 + E_bind[id]) @ W2 + b2) -> sec
        gemm<KB1, H, 1, false, true, false>(sm.xb_bind, g_CB1, nullptr, g_Ebind, sm.ids, sm.red,
                                            sm.hbuf, H, 0, nullptr, 0, 0, nullptr, 0);
        gemm<H, H, 2, true, false, false>(sm.hbuf, bind_W2, bind_b2, nullptr, nullptr, sm.red,
                                          sm.xb_router, 384, 0, sm.xb_succ, KS1, 0, nullptr, 0);

        // phase routing (smem weights): phw = softmax([sec,prev] @ router_W + b)
        gemm<384, PHH, 0, true, false, true>(sm.xb_router, sm.sWrtr, router_b, nullptr, nullptr,
                                             sm.red,
                                             sm.z16, PHH, 0, nullptr, 0, 0, nullptr, 0);
        softmax_rows<PHH>(sm.z16,
                          sm.xb_succ, KS1, H + PP,   // phw slot of succ1 input
                          sm.z16, PHH, 0,            // harmless self-write (keeps fan-out shape)
                          out_phw + (b0 * S_LEN + s) * PHH, S_LEN * PHH);
        __syncthreads();

        // successor (patch+phase folded): tanh(gelu([sec,pw,phw,0] @ CS1 + b1) @ W2 + b2) -> succ
        gemm<KS1, H, 1, true, false, false>(sm.xb_succ, g_CS1, succ_b1, nullptr, nullptr, sm.red,
                                            sm.hbuf, H, 0, nullptr, 0, 0, nullptr, 0);
        gemm<H, H, 2, true, false, false>(sm.hbuf, succ_W2, succ_b2, nullptr, nullptr, sm.red,
                                          sm.xb_gate, 384, 0, sm.succ, H, 0, nullptr, 0);

        // gate hidden layer: gelu([succ,prev] @ gW1 + b1)
        gemm<384, H, 1, true, false, false>(sm.xb_gate, gate_W1, gate_b1, nullptr, nullptr, sm.red,
                                            sm.hbuf, H, 0, nullptr, 0, 0, nullptr, 0);

        // fused: gate2 dot + sigmoid + hidden mix + layernorm + fan-out (4 warps)
        {
            const int w = t >> 5, lane = t & 31;
            if (w < BM) {
                float v = 0.f;
#pragma unroll
                for (int i = 0; i < H / 32; i++) {
                    const int k = lane + 32 * i;
                    v = fmaf(sm.hbuf[w * H + k], sm.sgw2[k], v);
                }
#pragma unroll
                for (int o = 16; o; o >>= 1) v += __shfl_xor_sync(0xffffffffu, v, o);
                v += sm.sgb2;
                const float g = 1.f / (1.f + expf(-v));
                if (lane == 0) out_gate[(b0 + w) * S_LEN + s] = g;

                float lv[H / 32];
                float mean = 0.f;
#pragma unroll
                for (int i = 0; i < H / 32; i++) {
                    const int h = lane + 32 * i;
                    float hv = g * sm.succ[w * H + h] + (1.f - g) * sm.prev[w * H + h];
                    lv[i] = hv; mean += hv;
                }
#pragma unroll
                for (int o = 16; o; o >>= 1) mean += __shfl_xor_sync(0xffffffffu, mean, o);
                mean *= (1.f / (float)H);
                float var = 0.f;
#pragma unroll
                for (int i = 0; i < H / 32; i++) { float d = lv[i] - mean; var = fmaf(d, d, var); }
#pragma unroll
                for (int o = 16; o; o >>= 1) var += __shfl_xor_sync(0xffffffffu, var, o);
                var *= (1.f / (float)H);
                const float rstd = rsqrtf(var + 1e-5f);
                float* oh = out_hidden + ((b0 + w) * S_LEN + s) * H;
#pragma unroll
                for (int i = 0; i < H / 32; i++) {
                    const int h = lane + 32 * i;
                    float o = (lv[i] - mean) * rstd * sm.slng[h] + sm.slnb[h];
                    sm.prev[w * H + h] = o;
                    sm.xb_dec[w * H + h] = o;
                    sm.xb_bind  [w * KB1 + h] = o;       // prev slot
                    sm.xb_router[w * 384 + H + h] = o;
                    sm.xb_gate  [w * 384 + H + h] = o;
                    oh[h] = o;
                }
            }
        }
        __syncthreads();

        // readout: logits = hidden @ dec_W
        gemm<H, VOC, 0, false, false, false>(sm.xb_dec, dec_W, nullptr, nullptr, nullptr, sm.red,
                                             nullptr, 0, 0, nullptr, 0, 0,
                                             out_logits + (b0 * S_LEN + s) * VOC, S_LEN * VOC);
    }
}

extern "C" void kernel_launch(void* const* d_in, const int* in_sizes, int n_in,
                              void* d_out, int out_size)
{
    const int*   ids          = (const int*)  d_in[0];
    const float* emb          = (const float*)d_in[1];
    const float* sel_W        = (const float*)d_in[2];
    const float* sel_b        = (const float*)d_in[3];
    const float* patch_values = (const float*)d_in[4];
    const float* bind_W1      = (const float*)d_in[5];
    const float* bind_b1      = (const float*)d_in[6];
    const float* bind_W2      = (const float*)d_in[7];
    const float* bind_b2      = (const float*)d_in[8];
    const float* phase_embed  = (const float*)d_in[9];
    const float* router_W     = (const float*)d_in[10];
    const float* router_b     = (const float*)d_in[11];
    const float* succ_W1      = (const float*)d_in[12];
    const float* succ_b1      = (const float*)d_in[13];
    const float* succ_W2      = (const float*)d_in[14];
    const float* succ_b2      = (const float*)d_in[15];
    const float* gate_W1      = (const float*)d_in[16];
    const float* gate_b1      = (const float*)d_in[17];
    const float* gate_W2      = (const float*)d_in[18];
    const float* gate_b2      = (const float*)d_in[19];
    const float* ln_g         = (const float*)d_in[20];
    const float* ln_b         = (const float*)d_in[21];
    const float* dec_W        = (const float*)d_in[22];

    // fold patch/phase projections + token projections
    prep_kernel<<<(PREP_TOTAL + 255) / 256, 256>>>(emb, patch_values, phase_embed,
                                                   sel_W, sel_b, bind_W1, bind_b1, succ_W1);

    spike_kernel<<<B_TOT / BM, TPB>>>(
        ids,
        sel_W + H * PP,                 // sel_W prev block (rows [H:2H))
        bind_W2, bind_b2,
        router_W, router_b,
        succ_b1, succ_W2, succ_b2,
        gate_W1, gate_b1, gate_W2, gate_b2,
        ln_g, ln_b, dec_W, (float*)d_out);
}

// round 17
// speedup vs baseline: 1.0245x; 1.0245x over previous
#include <cuda_runtime.h>
#include <math.h>

#define TPB   768
#define BM    4
#define S_LEN 128
#define B_TOT 512
#define H     192
#define VOC   256
#define PP    64
#define PHH   16

#define KB1   256   // folded bind1 K: [prev|pw]           (tok folded into E_bind)
#define KS1   320   // folded succ1 K: [sec|pw|phw|pad48]

// output buffer offsets (floats), concatenated in reference-return order
#define OFF_LOGITS 0
#define OFF_HIDDEN (512*128*256)
#define OFF_PW     (OFF_HIDDEN + 512*128*192)
#define OFF_PHW    (OFF_PW     + 512*128*64)
#define OFF_GATE   (OFF_PHW    + 512*128*16)

__device__ float g_CB1 [KB1 * H];   // folded bind1 weights ([prev|pw] blocks)
__device__ float g_CS1 [KS1 * H];   // folded succ1 weights
__device__ float g_Esel[VOC * PP];  // emb @ sel_W_tok + sel_b
__device__ float g_Ebind[VOC * H];  // emb @ bind_W1_tok + bind_b1

__device__ __forceinline__ float geluf(float x) {
    return 0.5f * x * (1.0f + erff(x * 0.7071067811865475f));
}

// ---------------------------------------------------------------------------
// prep: build folded weights + per-vocab token projections (once per launch)
// ---------------------------------------------------------------------------
#define PREP_TOTAL (KB1*H + KS1*H + VOC*PP + VOC*H)

__global__ void prep_kernel(const float* __restrict__ emb,
                            const float* __restrict__ pv,
                            const float* __restrict__ pe,
                            const float* __restrict__ selW,
                            const float* __restrict__ selb,
                            const float* __restrict__ bw1,
                            const float* __restrict__ bb1,
                            const float* __restrict__ sw1)
{
    int idx = blockIdx.x * blockDim.x + threadIdx.x;
    if (idx >= PREP_TOTAL) return;

    if (idx < KB1 * H) {                         // CB1: [prev(192) | pw(64)] x H
        const int row = idx / H, n = idx % H;
        float v;
        if (row < H) v = bw1[(2 * H + row) * H + n];          // prev block
        else {
            const int p = row - H;
            float a = 0.f, b = 0.f;
            for (int h = 0; h < H; h += 2) {
                a = fmaf(pv[p * H + h],     bw1[(H + h) * H + n],     a);
                b = fmaf(pv[p * H + h + 1], bw1[(H + h + 1) * H + n], b);
            }
            v = a + b;
        }
        g_CB1[row * H + n] = v;
        return;
    }
    idx -= KB1 * H;
    if (idx < KS1 * H) {                         // CS1: [sec|pw|phw|pad]
        const int r = idx / H, n = idx % H;
        float v;
        if (r < H) v = sw1[r * H + n];
        else if (r < H + PP) {
            const int p = r - H;
            float a = 0.f, b = 0.f;
            for (int h = 0; h < H; h += 2) {
                a = fmaf(pv[p * H + h],     sw1[(H + h) * H + n],     a);
                b = fmaf(pv[p * H + h + 1], sw1[(H + h + 1) * H + n], b);
            }
            v = a + b;
        } else if (r < H + PP + PHH) {
            const int q = r - H - PP;
            float a = 0.f, b = 0.f;
            for (int h = 0; h < H; h += 2) {
                a = fmaf(pe[q * H + h],     sw1[(2 * H + h) * H + n],     a);
                b = fmaf(pe[q * H + h + 1], sw1[(2 * H + h + 1) * H + n], b);
            }
            v = a + b;
        } else v = 0.f;
        g_CS1[r * H + n] = v;
        return;
    }
    idx -= KS1 * H;
    if (idx < VOC * PP) {                        // Esel = emb @ sel_W_tok + sel_b
        const int vid = idx / PP, n = idx % PP;
        float a = 0.f, b = 0.f;
        for (int h = 0; h < H; h += 2) {
            a = fmaf(emb[vid * H + h],     selW[h * PP + n],       a);
            b = fmaf(emb[vid * H + h + 1], selW[(h + 1) * PP + n], b);
        }
        g_Esel[vid * PP + n] = a + b + selb[n];
        return;
    }
    idx -= VOC * PP;
    {                                            // Ebind = emb @ bind_W1_tok + bind_b1
        const int vid = idx / H, n = idx % H;
        float a = 0.f, b = 0.f;
        for (int h = 0; h < H; h += 2) {
            a = fmaf(emb[vid * H + h],     bw1[h * H + n],       a);
            b = fmaf(emb[vid * H + h + 1], bw1[(h + 1) * H + n], b);
        }
        g_Ebind[vid * H + n] = a + b + bb1[n];
    }
}

struct __align__(16) Smem {
    float red [12288];          // k-split partial scratch: NSEG*BM*N == 12288 for all shapes
    float xb_bind [BM * KB1];   // [prev | pw]
    float xb_router[BM * 384];  // [sec | prev]
    float xb_succ [BM * KS1];   // [sec | pw | phw | pad]
    float xb_gate [BM * 384];   // [succ | prev]
    float xb_dec  [BM * H];     // hidden (also sel input)
    float hbuf [BM * H];        // bind1/succ1/gate1 intermediate
    float prev [BM * H];        // normal copy for LN
    float succ [BM * H];        // normal copy for LN
    float z64  [BM * PP];
    float z16  [BM * PHH];
    float sgw2 [H];             // gate_W2 cached in smem
    float slng [H];             // ln_g cached
    float slnb [H];             // ln_b cached
    float sWrtr[384 * PHH];     // router_W cached (24KB) — kills router-phase ramp
    float sgb2;                 // gate_b2 scalar
    int   ids  [BM];            // ids(s)
};

// C[BM x N] = act( X[BM x K] @ W[K x N] (+ bias | + rowbias[ids[r]]) )
// thread -> (col4 = t % (N/4), kseg = t / (N/4)); partials reduced through smem.
// ACT: 0 = none, 1 = gelu(exact), 2 = tanh.  WSM: weights live in shared memory.
template<int K, int N, int ACT, bool HASB, bool ROWB, bool WSM>
__device__ __forceinline__ void gemm(const float* __restrict__ xs,
                                     const float* __restrict__ W,
                                     const float* __restrict__ bias,
                                     const float* __restrict__ rbias,
                                     const int*   __restrict__ ids,
                                     float* __restrict__ red,
                                     float* __restrict__ o1, int rs1, int off1,
                                     float* __restrict__ o2, int rs2, int off2,
                                     float* __restrict__ outg, int g_rstride)
{
    constexpr int NC4  = N / 4;
    constexpr int NSEG = TPB / NC4;
    constexpr int KS   = K / NSEG;
    static_assert(NC4 * NSEG == TPB, "thread mapping must be exact");
    static_assert(KS * NSEG == K,    "k split must be exact");
    static_assert((NSEG % 2) == 0,   "epilogue 2-acc split must be exact");

    const int t   = threadIdx.x;
    const int c4  = t % NC4;
    const int seg = t / NC4;
    const float4* __restrict__ Wv = reinterpret_cast<const float4*>(W);

    auto ldw = [&](int idx) -> float4 {
        if (WSM) return Wv[idx];
        else     return __ldg(&Wv[idx]);
    };

    float4 acc[BM];
#pragma unroll
    for (int r = 0; r < BM; r++) acc[r] = make_float4(0.f, 0.f, 0.f, 0.f);

    const int k0 = seg * KS;

    if constexpr ((KS % 4) == 0) {
        const float4* __restrict__ Xv = reinterpret_cast<const float4*>(xs);
#pragma unroll 2
        for (int kk4 = 0; kk4 < KS / 4; kk4++) {
            const int k = k0 + kk4 * 4;
            float4 xv[BM];
#pragma unroll
            for (int r = 0; r < BM; r++) xv[r] = Xv[(r * K + k) >> 2];
            // all four weight loads issued up front -> deeper MLP on the LDG stream
            float4 w0 = ldw((k + 0) * NC4 + c4);
            float4 w1 = ldw((k + 1) * NC4 + c4);
            float4 w2 = ldw((k + 2) * NC4 + c4);
            float4 w3 = ldw((k + 3) * NC4 + c4);
#pragma unroll
            for (int r = 0; r < BM; r++) {
                acc[r].x = fmaf(xv[r].x, w0.x, acc[r].x);
                acc[r].y = fmaf(xv[r].x, w0.y, acc[r].y);
                acc[r].z = fmaf(xv[r].x, w0.z, acc[r].z);
                acc[r].w = fmaf(xv[r].x, w0.w, acc[r].w);
                acc[r].x = fmaf(xv[r].y, w1.x, acc[r].x);
                acc[r].y = fmaf(xv[r].y, w1.y, acc[r].y);
                acc[r].z = fmaf(xv[r].y, w1.z, acc[r].z);
                acc[r].w = fmaf(xv[r].y, w1.w, acc[r].w);
            }
#pragma unroll
            for (int r = 0; r < BM; r++) {
                acc[r].x = fmaf(xv[r].z, w2.x, acc[r].x);
                acc[r].y = fmaf(xv[r].z, w2.y, acc[r].y);
                acc[r].z = fmaf(xv[r].z, w2.z, acc[r].z);
                acc[r].w = fmaf(xv[r].z, w2.w, acc[r].w);
                acc[r].x = fmaf(xv[r].w, w3.x, acc[r].x);
                acc[r].y = fmaf(xv[r].w, w3.y, acc[r].y);
                acc[r].z = fmaf(xv[r].w, w3.z, acc[r].z);
                acc[r].w = fmaf(xv[r].w, w3.w, acc[r].w);
            }
        }
    } else {
#pragma unroll
        for (int kk = 0; kk < KS; kk++) {
            const int k = k0 + kk;
            float4 w = ldw(k * NC4 + c4);
#pragma unroll
            for (int r = 0; r < BM; r++) {
                float x = xs[r * K + k];
                acc[r].x = fmaf(x, w.x, acc[r].x);
                acc[r].y = fmaf(x, w.y, acc[r].y);
                acc[r].z = fmaf(x, w.z, acc[r].z);
                acc[r].w = fmaf(x, w.w, acc[r].w);
            }
        }
    }

    float4* redv = reinterpret_cast<float4*>(red);
#pragma unroll
    for (int r = 0; r < BM; r++) redv[(seg * BM + r) * NC4 + c4] = acc[r];
    __syncthreads();

    for (int i = t; i < BM * N; i += TPB) {
        const int r = i / N;
        const int n = i % N;
        float v;
        if constexpr ((NSEG % 4) == 0) {
            float v0 = 0.f, v1 = 0.f, v2 = 0.f, v3 = 0.f;
#pragma unroll
            for (int g = 0; g < NSEG; g += 4) {
                v0 += red[((g + 0) * BM + r) * N + n];
                v1 += red[((g + 1) * BM + r) * N + n];
                v2 += red[((g + 2) * BM + r) * N + n];
                v3 += red[((g + 3) * BM + r) * N + n];
            }
            v = (v0 + v1) + (v2 + v3);
        } else {
            float v0 = 0.f, v1 = 0.f;
#pragma unroll
            for (int g = 0; g < NSEG; g += 2) {
                v0 += red[((g + 0) * BM + r) * N + n];
                v1 += red[((g + 1) * BM + r) * N + n];
            }
            v = v0 + v1;
        }
        if (HASB) v += __ldg(&bias[n]);
        if (ROWB) v += __ldg(&rbias[ids[r] * N + n]);
        if (ACT == 1) v = geluf(v);
        if (ACT == 2) v = tanhf(v);
        if (o1) o1[r * rs1 + off1 + n] = v;
        if (o2) o2[r * rs2 + off2 + n] = v;
        if (outg) outg[r * g_rstride + n] = v;
    }
    __syncthreads();
}

// warp-per-row softmax over N (<= 64): fan-out to two smem slots + global
template<int N>
__device__ __forceinline__ void softmax_rows(const float* __restrict__ z,
                                             float* __restrict__ o1, int rs1, int off1,
                                             float* __restrict__ o2, int rs2, int off2,
                                             float* __restrict__ outg, int g_rstride)
{
    const int w = threadIdx.x >> 5, lane = threadIdx.x & 31;
    if (w < BM) {
        const float* row = z + w * N;
        constexpr int PER = (N + 31) / 32;
        float m = -3.0e38f;
#pragma unroll
        for (int i = 0; i < PER; i++) {
            int n = lane + 32 * i;
            if (n < N) m = fmaxf(m, row[n]);
        }
#pragma unroll
        for (int o = 16; o; o >>= 1) m = fmaxf(m, __shfl_xor_sync(0xffffffffu, m, o));
        float ev[PER];
        float sum = 0.f;
#pragma unroll
        for (int i = 0; i < PER; i++) {
            int n = lane + 32 * i;
            if (n < N) { ev[i] = expf(row[n] - m); sum += ev[i]; }
        }
#pragma unroll
        for (int o = 16; o; o >>= 1) sum += __shfl_xor_sync(0xffffffffu, sum, o);
        const float inv = 1.f / sum;
#pragma unroll
        for (int i = 0; i < PER; i++) {
            int n = lane + 32 * i;
            if (n < N) {
                float v = ev[i] * inv;
                o1[w * rs1 + off1 + n] = v;
                o2[w * rs2 + off2 + n] = v;
                outg[w * g_rstride + n] = v;
            }
        }
    }
}

__global__ void __launch_bounds__(TPB, 1)
spike_kernel(const int* __restrict__ ids_g,
             const float* __restrict__ selW_prev,            // sel_W rows [H:2H)
             const float* __restrict__ bind_W2,  const float* __restrict__ bind_b2,
             const float* __restrict__ router_W, const float* __restrict__ router_b,
             const float* __restrict__ succ_b1,
             const float* __restrict__ succ_W2,  const float* __restrict__ succ_b2,
             const float* __restrict__ gate_W1,  const float* __restrict__ gate_b1,
             const float* __restrict__ gate_W2,  const float* __restrict__ gate_b2,
             const float* __restrict__ ln_g,     const float* __restrict__ ln_b,
             const float* __restrict__ dec_W,
             float* __restrict__ out)
{
    __shared__ Smem sm;
    const int t  = threadIdx.x;
    const int b0 = blockIdx.x * BM;

    float* out_logits = out + OFF_LOGITS;
    float* out_hidden = out + OFF_HIDDEN;
    float* out_pw     = out + OFF_PW;
    float* out_phw    = out + OFF_PHW;
    float* out_gate   = out + OFF_GATE;

    // init: zero prev slots + hidden + succ1 pad ; cache small vectors + router weights
    {
        const int r = t / H, h = t % H;
        sm.prev[t] = 0.f;
        sm.xb_dec[t] = 0.f;
        sm.xb_bind  [r * KB1 + h] = 0.f;       // prev slot of bind input
        sm.xb_router[r * 384 + H + h] = 0.f;
        sm.xb_gate  [r * 384 + H + h] = 0.f;
        if (t < H) {
            sm.sgw2[t] = __ldg(&gate_W2[t]);
            sm.slng[t] = __ldg(&ln_g[t]);
            sm.slnb[t] = __ldg(&ln_b[t]);
        }
        if (t == 0) sm.sgb2 = __ldg(&gate_b2[0]);
        if (t < BM * 48) {                      // pad slots [272:320) of xb_succ
            const int rr = t / 48, i = t % 48;
            sm.xb_succ[rr * KS1 + 272 + i] = 0.f;
        }
        // cache router weights in smem (float4 copies)
        const float4* gr = reinterpret_cast<const float4*>(router_W);
        float4*       dr = reinterpret_cast<float4*>(sm.sWrtr);
        for (int i = t; i < (384 * PHH) / 4; i += TPB) dr[i] = __ldg(&gr[i]);
    }
    __syncthreads();

    for (int s = 0; s < S_LEN; s++) {
        // stage ids(s); published by the sel gemm's internal barrier
        if (t < BM) sm.ids[t] = __ldg(&ids_g[(b0 + t) * S_LEN + s]);

        // patch selector (tok folded): pw = softmax(prev @ selW_prev + E_sel[id])
        gemm<H, PP, 0, false, true, false>(sm.xb_dec, selW_prev, nullptr, g_Esel, sm.ids, sm.red,
                                           sm.z64, PP, 0, nullptr, 0, 0, nullptr, 0);
        softmax_rows<PP>(sm.z64,
                         sm.xb_bind, KB1, H,         // pw slot of bind1 input
                         sm.xb_succ, KS1, H,         // pw slot of succ1 input
                         out_pw + (b0 * S_LEN + s) * PP, S_LEN * PP);
        __syncthreads();

        // section binder (tok+patch folded): tanh(gelu([prev,pw]@CB1 + E_bind[id]) @ W2 + b2) -> sec
        gemm<KB1, H, 1, false, true, false>(sm.xb_bind, g_CB1, nullptr, g_Ebind, sm.ids, sm.red,
                                            sm.hbuf, H, 0, nullptr, 0, 0, nullptr, 0);
        gemm<H, H, 2, true, false, false>(sm.hbuf, bind_W2, bind_b2, nullptr, nullptr, sm.red,
                                          sm.xb_router, 384, 0, sm.xb_succ, KS1, 0, nullptr, 0);

        // phase routing (smem weights): phw = softmax([sec,prev] @ router_W + b)
        gemm<384, PHH, 0, true, false, true>(sm.xb_router, sm.sWrtr, router_b, nullptr, nullptr,
                                             sm.red,
                                             sm.z16, PHH, 0, nullptr, 0, 0, nullptr, 0);
        softmax_rows<PHH>(sm.z16,
                          sm.xb_succ, KS1, H + PP,   // phw slot of succ1 input
                          sm.z16, PHH, 0,            // harmless self-write (keeps fan-out shape)
                          out_phw + (b0 * S_LEN + s) * PHH, S_LEN * PHH);
        __syncthreads();

        // successor (patch+phase folded): tanh(gelu([sec,pw,phw,0] @ CS1 + b1) @ W2 + b2) -> succ
        gemm<KS1, H, 1, true, false, false>(sm.xb_succ, g_CS1, succ_b1, nullptr, nullptr, sm.red,
                                            sm.hbuf, H, 0, nullptr, 0, 0, nullptr, 0);
        gemm<H, H, 2, true, false, false>(sm.hbuf, succ_W2, succ_b2, nullptr, nullptr, sm.red,
                                          sm.xb_gate, 384, 0, sm.succ, H, 0, nullptr, 0);

        // gate hidden layer: gelu([succ,prev] @ gW1 + b1)
        gemm<384, H, 1, true, false, false>(sm.xb_gate, gate_W1, gate_b1, nullptr, nullptr, sm.red,
                                            sm.hbuf, H, 0, nullptr, 0, 0, nullptr, 0);

        // fused: gate2 dot + sigmoid + hidden mix + layernorm + fan-out (4 warps)
        {
            const int w = t >> 5, lane = t & 31;
            if (w < BM) {
                float v = 0.f;
#pragma unroll
                for (int i = 0; i < H / 32; i++) {
                    const int k = lane + 32 * i;
                    v = fmaf(sm.hbuf[w * H + k], sm.sgw2[k], v);
                }
#pragma unroll
                for (int o = 16; o; o >>= 1) v += __shfl_xor_sync(0xffffffffu, v, o);
                v += sm.sgb2;
                const float g = 1.f / (1.f + expf(-v));
                if (lane == 0) out_gate[(b0 + w) * S_LEN + s] = g;

                float lv[H / 32];
                float mean = 0.f;
#pragma unroll
                for (int i = 0; i < H / 32; i++) {
                    const int h = lane + 32 * i;
                    float hv = g * sm.succ[w * H + h] + (1.f - g) * sm.prev[w * H + h];
                    lv[i] = hv; mean += hv;
                }
#pragma unroll
                for (int o = 16; o; o >>= 1) mean += __shfl_xor_sync(0xffffffffu, mean, o);
                mean *= (1.f / (float)H);
                float var = 0.f;
#pragma unroll
                for (int i = 0; i < H / 32; i++) { float d = lv[i] - mean; var = fmaf(d, d, var); }
#pragma unroll
                for (int o = 16; o; o >>= 1) var += __shfl_xor_sync(0xffffffffu, var, o);
                var *= (1.f / (float)H);
                const float rstd = rsqrtf(var + 1e-5f);
                float* oh = out_hidden + ((b0 + w) * S_LEN + s) * H;
#pragma unroll
                for (int i = 0; i < H / 32; i++) {
                    const int h = lane + 32 * i;
                    float o = (lv[i] - mean) * rstd * sm.slng[h] + sm.slnb[h];
                    sm.prev[w * H + h] = o;
                    sm.xb_dec[w * H + h] = o;
                    sm.xb_bind  [w * KB1 + h] = o;       // prev slot
                    sm.xb_router[w * 384 + H + h] = o;
                    sm.xb_gate  [w * 384 + H + h] = o;
                    oh[h] = o;
                }
            }
        }
        __syncthreads();

        // readout: logits = hidden @ dec_W
        gemm<H, VOC, 0, false, false, false>(sm.xb_dec, dec_W, nullptr, nullptr, nullptr, sm.red,
                                             nullptr, 0, 0, nullptr, 0, 0,
                                             out_logits + (b0 * S_LEN + s) * VOC, S_LEN * VOC);
    }
}

extern "C" void kernel_launch(void* const* d_in, const int* in_sizes, int n_in,
                              void* d_out, int out_size)
{
    const int*   ids          = (const int*)  d_in[0];
    const float* emb          = (const float*)d_in[1];
    const float* sel_W        = (const float*)d_in[2];
    const float* sel_b        = (const float*)d_in[3];
    const float* patch_values = (const float*)d_in[4];
    const float* bind_W1      = (const float*)d_in[5];
    const float* bind_b1      = (const float*)d_in[6];
    const float* bind_W2      = (const float*)d_in[7];
    const float* bind_b2      = (const float*)d_in[8];
    const float* phase_embed  = (const float*)d_in[9];
    const float* router_W     = (const float*)d_in[10];
    const float* router_b     = (const float*)d_in[11];
    const float* succ_W1      = (const float*)d_in[12];
    const float* succ_b1      = (const float*)d_in[13];
    const float* succ_W2      = (const float*)d_in[14];
    const float* succ_b2      = (const float*)d_in[15];
    const float* gate_W1      = (const float*)d_in[16];
    const float* gate_b1      = (const float*)d_in[17];
    const float* gate_W2      = (const float*)d_in[18];
    const float* gate_b2      = (const float*)d_in[19];
    const float* ln_g         = (const float*)d_in[20];
    const float* ln_b         = (const float*)d_in[21];
    const float* dec_W        = (const float*)d_in[22];

    // fold patch/phase projections + token projections
    prep_kernel<<<(PREP_TOTAL + 255) / 256, 256>>>(emb, patch_values, phase_embed,
                                                   sel_W, sel_b, bind_W1, bind_b1, succ_W1);

    spike_kernel<<<B_TOT / BM, TPB>>>(
        ids,
        sel_W + H * PP,                 // sel_W prev block (rows [H:2H))
        bind_W2, bind_b2,
        router_W, router_b,
        succ_b1, succ_W2, succ_b2,
        gate_W1, gate_b1, gate_W2, gate_b2,
        ln_g, ln_b, dec_W, (float*)d_out);
}